// round 1
// baseline (speedup 1.0000x reference)
#include <cuda_runtime.h>

// Problem constants
#define B_    4
#define C_    256
#define S_    1024        // H*W = 32*32
#define HEADS_ 8
#define D_    32          // C/HEADS
#define GROUPS_ 32
#define CPG_  8           // C/GROUPS
#define EPS_  1e-5f
#define SCALE_ 0.17677669529663687f   // 1/sqrt(32)

// Scratch (static device arrays — no allocation allowed)
__device__ float g_xn[B_ * C_ * S_];            // 4 MB   groupnorm output [b][c][s]
__device__ float g_qkv[B_ * 3 * C_ * S_];       // 12 MB  [b][3*C][s]
__device__ float g_scores[B_ * HEADS_ * S_ * S_]; // 128 MB  [bh][i][j]
__device__ float g_att[B_ * C_ * S_];           // 4 MB   attention out [b][c][s]

// ---------------------------------------------------------------------------
// GroupNorm: one block per (b, group). 8 channels x 1024 = 8192 floats/group.
// ---------------------------------------------------------------------------
__global__ void gn_kernel(const float* __restrict__ x,
                          const float* __restrict__ gamma,
                          const float* __restrict__ beta) {
    int bg = blockIdx.x;                 // 0..127
    int b = bg / GROUPS_, g = bg % GROUPS_;
    const float4* x4 = (const float4*)(x + ((size_t)b * C_ + g * CPG_) * S_);
    float4* o4 = (float4*)(g_xn + ((size_t)b * C_ + g * CPG_) * S_);
    int tid = threadIdx.x;               // 256 threads

    float s0 = 0.f, s1 = 0.f;
    #pragma unroll
    for (int i = tid; i < 2048; i += 256) {   // 2048 float4 = 8192 floats
        float4 v = x4[i];
        s0 += v.x + v.y + v.z + v.w;
        s1 += v.x * v.x + v.y * v.y + v.z * v.z + v.w * v.w;
    }
    __shared__ float r0[256], r1[256];
    r0[tid] = s0; r1[tid] = s1;
    __syncthreads();
    for (int s = 128; s > 0; s >>= 1) {
        if (tid < s) { r0[tid] += r0[tid + s]; r1[tid] += r1[tid + s]; }
        __syncthreads();
    }
    __shared__ float s_mu, s_inv;
    if (tid == 0) {
        float m = r0[0] * (1.f / 8192.f);
        float v = r1[0] * (1.f / 8192.f) - m * m;
        s_mu = m;
        s_inv = rsqrtf(v + EPS_);
    }
    __syncthreads();
    float mu = s_mu, inv = s_inv;
    #pragma unroll
    for (int i = tid; i < 2048; i += 256) {
        int c = g * CPG_ + (i >> 8);     // 256 float4 per channel
        float ga = gamma[c] * inv;
        float be = beta[c] - mu * ga;
        float4 v = x4[i];
        v.x = v.x * ga + be; v.y = v.y * ga + be;
        v.z = v.z * ga + be; v.w = v.w * ga + be;
        o4[i] = v;
    }
}

// ---------------------------------------------------------------------------
// Generic GEMM: Out[b][m][n] = sum_k W[m][k] * X[b][k][n]  (+ bias + resid)
// BM=128, BN=64, BK=16, 256 threads, 8x4 microtile.
// ---------------------------------------------------------------------------
template <int M, int N, int K, bool PROJ>
__global__ __launch_bounds__(256) void gemm_kernel(
    const float* __restrict__ W, const float* __restrict__ Xbase,
    float* __restrict__ Out,
    const float* __restrict__ bias, const float* __restrict__ resid) {
    const int BM = 128, BN = 64, BK = 16;
    __shared__ float As[BK][BM + 4];
    __shared__ float Bs[BK][BN];

    int b  = blockIdx.z;
    int m0 = blockIdx.y * BM;
    int n0 = blockIdx.x * BN;
    const float* X = Xbase + (size_t)b * K * N;
    int tid = threadIdx.x;
    int tm = (tid / 16) * 8;   // 16 m-groups
    int tn = (tid % 16) * 4;   // 16 n-groups

    float acc[8][4] = {};

    for (int k0 = 0; k0 < K; k0 += BK) {
        // A tile: 128 rows x 16 k  (512 float4, 2 per thread), transposed store
        #pragma unroll
        for (int t = 0; t < 2; t++) {
            int idx = tid + t * 256;
            int row = idx >> 2;
            int c4  = (idx & 3) * 4;
            float4 v = *(const float4*)(W + (size_t)(m0 + row) * K + k0 + c4);
            As[c4 + 0][row] = v.x; As[c4 + 1][row] = v.y;
            As[c4 + 2][row] = v.z; As[c4 + 3][row] = v.w;
        }
        // B tile: 16 rows x 64 n (256 float4, 1 per thread)
        {
            int row = tid >> 4;
            int c4  = (tid & 15) * 4;
            *(float4*)&Bs[row][c4] =
                *(const float4*)(X + (size_t)(k0 + row) * N + n0 + c4);
        }
        __syncthreads();
        #pragma unroll
        for (int k = 0; k < BK; k++) {
            float a[8], bb[4];
            #pragma unroll
            for (int i = 0; i < 8; i++) a[i] = As[k][tm + i];
            #pragma unroll
            for (int j = 0; j < 4; j++) bb[j] = Bs[k][tn + j];
            #pragma unroll
            for (int i = 0; i < 8; i++)
                #pragma unroll
                for (int j = 0; j < 4; j++)
                    acc[i][j] += a[i] * bb[j];
        }
        __syncthreads();
    }

    #pragma unroll
    for (int i = 0; i < 8; i++) {
        int m = m0 + tm + i;
        float bia = PROJ ? bias[m] : 0.f;
        #pragma unroll
        for (int j = 0; j < 4; j++) {
            int n = n0 + tn + j;
            size_t o = (size_t)b * M * N + (size_t)m * N + n;
            float v = acc[i][j] + bia;
            if (PROJ) v += resid[o];
            Out[o] = v;
        }
    }
}

// ---------------------------------------------------------------------------
// Scores: S[bh][i][j] = scale * sum_d q[bh][i][d] * k[bh][j][d]
// q[d][s] / k[d][s] already d-major in g_qkv. 64x64 tile, K=32 in one shot.
// ---------------------------------------------------------------------------
__global__ __launch_bounds__(256) void score_kernel() {
    int bh = blockIdx.z;
    int b = bh / HEADS_, h = bh % HEADS_;
    int i0 = blockIdx.y * 64, j0 = blockIdx.x * 64;
    const float* qb = g_qkv + ((size_t)b * 3 * C_ + h * D_) * S_;
    const float* kb = g_qkv + ((size_t)b * 3 * C_ + C_ + h * D_) * S_;

    __shared__ float Qs[D_][64];   // [d][i]
    __shared__ float Ks[D_][64];   // [d][j]
    int tid = threadIdx.x;
    #pragma unroll
    for (int t = 0; t < 2; t++) {    // 512 float4 per operand, 2 per thread
        int idx = tid + t * 256;
        int d  = idx >> 4;
        int c4 = (idx & 15) * 4;
        *(float4*)&Qs[d][c4] = *(const float4*)(qb + (size_t)d * S_ + i0 + c4);
        *(float4*)&Ks[d][c4] = *(const float4*)(kb + (size_t)d * S_ + j0 + c4);
    }
    __syncthreads();

    int ti = (tid / 16) * 4, tj = (tid % 16) * 4;
    float acc[4][4] = {};
    #pragma unroll
    for (int d = 0; d < D_; d++) {
        float a[4], bb[4];
        #pragma unroll
        for (int u = 0; u < 4; u++) a[u] = Qs[d][ti + u];
        #pragma unroll
        for (int w = 0; w < 4; w++) bb[w] = Ks[d][tj + w];
        #pragma unroll
        for (int u = 0; u < 4; u++)
            #pragma unroll
            for (int w = 0; w < 4; w++)
                acc[u][w] += a[u] * bb[w];
    }
    float* sp = g_scores + (size_t)bh * S_ * S_;
    #pragma unroll
    for (int u = 0; u < 4; u++)
        #pragma unroll
        for (int w = 0; w < 4; w++)
            sp[(size_t)(i0 + ti + u) * S_ + j0 + tj + w] = acc[u][w] * SCALE_;
}

// ---------------------------------------------------------------------------
// Softmax over each row of 1024. One block per row, 256 threads, float4.
// ---------------------------------------------------------------------------
__global__ __launch_bounds__(256) void softmax_kernel() {
    size_t row = blockIdx.x;
    float4* rp = (float4*)(g_scores + row * (size_t)S_);
    int tid = threadIdx.x;
    float4 v = rp[tid];

    __shared__ float red[256];
    float mx = fmaxf(fmaxf(v.x, v.y), fmaxf(v.z, v.w));
    red[tid] = mx;
    __syncthreads();
    for (int s = 128; s > 0; s >>= 1) {
        if (tid < s) red[tid] = fmaxf(red[tid], red[tid + s]);
        __syncthreads();
    }
    mx = red[0];
    __syncthreads();

    v.x = __expf(v.x - mx); v.y = __expf(v.y - mx);
    v.z = __expf(v.z - mx); v.w = __expf(v.w - mx);
    red[tid] = v.x + v.y + v.z + v.w;
    __syncthreads();
    for (int s = 128; s > 0; s >>= 1) {
        if (tid < s) red[tid] += red[tid + s];
        __syncthreads();
    }
    float inv = 1.f / red[0];
    v.x *= inv; v.y *= inv; v.z *= inv; v.w *= inv;
    rp[tid] = v;
}

// ---------------------------------------------------------------------------
// O = P @ V : O[bh][i][d] = sum_j P[i][j] * v[d][j]; write as [b][c][s].
// BM=128 (i), full D=32 as N, BK=32. 256 threads, 4x4 microtile.
// ---------------------------------------------------------------------------
__global__ __launch_bounds__(256) void pv_kernel() {
    int bh = blockIdx.z;
    int b = bh / HEADS_, h = bh % HEADS_;
    int i0 = blockIdx.x * 128;
    const float* P = g_scores + (size_t)bh * S_ * S_;
    const float* vb = g_qkv + ((size_t)b * 3 * C_ + 2 * C_ + h * D_) * S_; // v[d][s]

    __shared__ float Ps[128][33];  // [i][j], padded
    __shared__ float Vs[32][33];   // [j][d], padded
    int tid = threadIdx.x;
    int ti = (tid / 8) * 4;        // 32 i-groups
    int td = (tid % 8) * 4;        // 8 d-groups
    float acc[4][4] = {};

    for (int j0 = 0; j0 < S_; j0 += 32) {
        // P tile: 128 rows x 32 j = 1024 float4, 4 per thread
        #pragma unroll
        for (int t = 0; t < 4; t++) {
            int idx = tid + t * 256;
            int r  = idx >> 3;
            int c4 = (idx & 7) * 4;
            float4 val = *(const float4*)(P + (size_t)(i0 + r) * S_ + j0 + c4);
            Ps[r][c4 + 0] = val.x; Ps[r][c4 + 1] = val.y;
            Ps[r][c4 + 2] = val.z; Ps[r][c4 + 3] = val.w;
        }
        // V tile transposed: Vs[j][d] = v[d][j0+j]; 1024 floats, 4 per thread
        #pragma unroll
        for (int t = 0; t < 4; t++) {
            int idx = tid + t * 256;
            int d = idx >> 5;
            int j = idx & 31;
            Vs[j][d] = vb[(size_t)d * S_ + j0 + j];
        }
        __syncthreads();
        #pragma unroll
        for (int j = 0; j < 32; j++) {
            float a[4], vv[4];
            #pragma unroll
            for (int u = 0; u < 4; u++) a[u] = Ps[ti + u][j];
            #pragma unroll
            for (int w = 0; w < 4; w++) vv[w] = Vs[j][td + w];
            #pragma unroll
            for (int u = 0; u < 4; u++)
                #pragma unroll
                for (int w = 0; w < 4; w++)
                    acc[u][w] += a[u] * vv[w];
        }
        __syncthreads();
    }
    float* ob = g_att + ((size_t)b * C_ + h * D_) * S_;
    #pragma unroll
    for (int w = 0; w < 4; w++)
        #pragma unroll
        for (int u = 0; u < 4; u++)
            ob[(size_t)(td + w) * S_ + i0 + ti + u] = acc[u][w];
}

// ---------------------------------------------------------------------------
extern "C" void kernel_launch(void* const* d_in, const int* in_sizes, int n_in,
                              void* d_out, int out_size) {
    const float* x      = (const float*)d_in[0];
    const float* gamma  = (const float*)d_in[1];
    const float* beta   = (const float*)d_in[2];
    const float* w_qkv  = (const float*)d_in[3];
    const float* w_proj = (const float*)d_in[4];
    const float* b_proj = (const float*)d_in[5];
    float* out = (float*)d_out;

    float* xn;     cudaGetSymbolAddress((void**)&xn, g_xn);
    float* qkv;    cudaGetSymbolAddress((void**)&qkv, g_qkv);
    float* att;    cudaGetSymbolAddress((void**)&att, g_att);

    // 1. GroupNorm
    gn_kernel<<<B_ * GROUPS_, 256>>>(x, gamma, beta);

    // 2. QKV GEMM: [768 x 256] @ [256 x 1024] per batch
    {
        dim3 grid(S_ / 64, (3 * C_) / 128, B_);
        gemm_kernel<3 * C_, S_, C_, false><<<grid, 256>>>(
            w_qkv, xn, qkv, nullptr, nullptr);
    }

    // 3. Scores = scale * Q K^T  (32 bh pairs)
    {
        dim3 grid(S_ / 64, S_ / 64, B_ * HEADS_);
        score_kernel<<<grid, 256>>>();
    }

    // 4. Row softmax
    softmax_kernel<<<B_ * HEADS_ * S_, 256>>>();

    // 5. O = P V  (write [b][c][s])
    {
        dim3 grid(S_ / 128, 1, B_ * HEADS_);
        pv_kernel<<<grid, 256>>>();
    }

    // 6. Proj + bias + residual
    {
        dim3 grid(S_ / 64, C_ / 128, B_);
        gemm_kernel<C_, S_, C_, true><<<grid, 256>>>(
            w_proj, att, out, b_proj, x);
    }
}

// round 2
// speedup vs baseline: 1.3562x; 1.3562x over previous
#include <cuda_runtime.h>

#define B_    4
#define C_    256
#define S_    1024
#define HEADS_ 8
#define D_    32
#define GROUPS_ 32
#define CPG_  8
#define EPS_  1e-5f
#define SCALE_ 0.17677669529663687f
#define KK2   (SCALE_ * 1.4426950408889634f)   // scale * log2(e)

typedef unsigned long long u64;

// Scratch
__device__ float g_qkv[B_ * 3 * C_ * S_];   // [b][768][1024]
__device__ float g_att[B_ * C_ * S_];       // [b][256][1024]
__device__ float g_coefA[B_ * C_];
__device__ float g_coefB[B_ * C_];

// ---------------------------------------------------------------------------
// f32x2 helpers
// ---------------------------------------------------------------------------
__device__ __forceinline__ u64 pk2(float lo, float hi) {
    u64 r; asm("mov.b64 %0, {%1, %2};" : "=l"(r) : "f"(lo), "f"(hi)); return r;
}
__device__ __forceinline__ void upk2(float& lo, float& hi, u64 v) {
    asm("mov.b64 {%0, %1}, %2;" : "=f"(lo), "=f"(hi) : "l"(v));
}
__device__ __forceinline__ void fma2(u64& d, u64 a, u64 b) {
    asm("fma.rn.f32x2 %0, %1, %2, %0;" : "+l"(d) : "l"(a), "l"(b));
}
__device__ __forceinline__ void mul2(u64& d, u64 a) {
    asm("mul.rn.f32x2 %0, %1, %0;" : "+l"(d) : "l"(a));
}
__device__ __forceinline__ float ex2(float x) {
    float r; asm("ex2.approx.ftz.f32 %0, %1;" : "=f"(r) : "f"(x)); return r;
}

// ---------------------------------------------------------------------------
// GroupNorm stats -> per-channel affine coefficients (no normalized tensor)
// ---------------------------------------------------------------------------
__global__ __launch_bounds__(256) void gnstat_kernel(
    const float* __restrict__ x, const float* __restrict__ gamma,
    const float* __restrict__ beta) {
    int bg = blockIdx.x;
    int b = bg >> 5, g = bg & 31;
    const float4* x4 = (const float4*)(x + ((size_t)b * C_ + g * CPG_) * S_);
    int tid = threadIdx.x;
    float s0 = 0.f, s1 = 0.f;
    #pragma unroll
    for (int i = tid; i < 2048; i += 256) {
        float4 v = x4[i];
        s0 += v.x + v.y + v.z + v.w;
        s1 += v.x * v.x + v.y * v.y + v.z * v.z + v.w * v.w;
    }
    __shared__ float r0[256], r1[256];
    r0[tid] = s0; r1[tid] = s1;
    __syncthreads();
    for (int s = 128; s > 0; s >>= 1) {
        if (tid < s) { r0[tid] += r0[tid + s]; r1[tid] += r1[tid + s]; }
        __syncthreads();
    }
    if (tid < 8) {
        float m = r0[0] * (1.f / 8192.f);
        float var = r1[0] * (1.f / 8192.f) - m * m;
        float inv = rsqrtf(var + EPS_);
        int c = g * CPG_ + tid;
        float ga = gamma[c] * inv;
        g_coefA[b * C_ + c] = ga;
        g_coefB[b * C_ + c] = beta[c] - m * ga;
    }
}

// ---------------------------------------------------------------------------
// f32x2 GEMM: Out[b][m][n] = sum_k W[m][k] * X'[b][k][n]
// X' = AFFINE ? (X * coefA[k] + coefB[k]) : X.  PROJ adds bias + residual.
// BN = 128, BK = 16, 256 threads, microtile RM x 8 (as RM/2 x 4 f32x2 pairs).
// ---------------------------------------------------------------------------
template <int BM, int RM, bool PROJ, bool AFFINE>
__global__ __launch_bounds__(256) void gemm_f2(
    const float* __restrict__ W, const float* __restrict__ X,
    float* __restrict__ Out,
    const float* __restrict__ bias, const float* __restrict__ resid,
    int M, int K) {
    const int BK = 16;
    __shared__ float As[BK][BM + 4];
    __shared__ float Bs[BK][128];

    int b = blockIdx.z;
    int m0 = blockIdx.y * BM;
    int n0 = blockIdx.x * 128;
    const float* Xb = X + (size_t)b * K * S_;
    const float* cA = AFFINE ? (g_coefA + b * C_) : nullptr;
    const float* cB = AFFINE ? (g_coefB + b * C_) : nullptr;
    int tid = threadIdx.x;
    int rg = tid >> 4, cg = tid & 15;

    u64 acc[RM][4] = {};

    for (int k0 = 0; k0 < K; k0 += BK) {
        #pragma unroll
        for (int t = 0; t < BM / 64; t++) {
            int idx = tid + t * 256;
            int row = idx >> 2;
            int kq = (idx & 3) * 4;
            float4 v = *(const float4*)&W[(size_t)(m0 + row) * K + k0 + kq];
            As[kq + 0][row] = v.x; As[kq + 1][row] = v.y;
            As[kq + 2][row] = v.z; As[kq + 3][row] = v.w;
        }
        #pragma unroll
        for (int t = 0; t < 2; t++) {
            int idx = tid + t * 256;
            int row = idx >> 5;
            int n4 = (idx & 31) * 4;
            float4 v = *(const float4*)&Xb[(size_t)(k0 + row) * S_ + n0 + n4];
            if (AFFINE) {
                int c = k0 + row;
                float a = cA[c], be = cB[c];
                v.x = fmaf(v.x, a, be); v.y = fmaf(v.y, a, be);
                v.z = fmaf(v.z, a, be); v.w = fmaf(v.w, a, be);
            }
            *(float4*)&Bs[row][n4] = v;
        }
        __syncthreads();
        #pragma unroll
        for (int k = 0; k < BK; k++) {
            float4 b0 = *(float4*)&Bs[k][cg * 8];
            float4 b1 = *(float4*)&Bs[k][cg * 8 + 4];
            u64 bp[4] = { pk2(b0.x, b0.y), pk2(b0.z, b0.w),
                          pk2(b1.x, b1.y), pk2(b1.z, b1.w) };
            float a[RM];
            #pragma unroll
            for (int t = 0; t < RM / 4; t++) {
                float4 av = *(float4*)&As[k][rg * RM + t * 4];
                a[t * 4 + 0] = av.x; a[t * 4 + 1] = av.y;
                a[t * 4 + 2] = av.z; a[t * 4 + 3] = av.w;
            }
            #pragma unroll
            for (int i = 0; i < RM; i++) {
                u64 ab = pk2(a[i], a[i]);
                #pragma unroll
                for (int jp = 0; jp < 4; jp++) fma2(acc[i][jp], ab, bp[jp]);
            }
        }
        __syncthreads();
    }

    #pragma unroll
    for (int i = 0; i < RM; i++) {
        int m = m0 + rg * RM + i;
        float bia = PROJ ? bias[m] : 0.f;
        #pragma unroll
        for (int jp = 0; jp < 4; jp++) {
            float lo, hi;
            upk2(lo, hi, acc[i][jp]);
            int n = n0 + cg * 8 + jp * 2;
            size_t o = ((size_t)b * M + m) * S_ + n;
            lo += bia; hi += bia;
            if (PROJ) { lo += resid[o]; hi += resid[o + 1]; }
            Out[o] = lo; Out[o + 1] = hi;
        }
    }
}

// ---------------------------------------------------------------------------
// Fused flash attention. Block = (bh, 128-query tile). 256 threads.
// Smem: Qs/Ks/Vs [32][132] d-major; Ps [128 j][132] j-major; row stats.
// QK microtile: rows rg*8..+7 (pairs), cols cg + 16*jj (jj<8).
// PV microtile: rows rg2*4..+3 (pairs), cols d = cg2 + 8*w (w<4).
// ---------------------------------------------------------------------------
__global__ __launch_bounds__(256) void flash_kernel() {
    extern __shared__ float sh[];
    float* Qs = sh;                 // 32*132
    float* Ks = Qs + 32 * 132;
    float* Vs = Ks + 32 * 132;
    float* Ps = Vs + 32 * 132;      // 128*132
    float* smx = Ps + 128 * 132;    // [128]
    float* sl  = smx + 128;         // [128]
    float* sc  = sl + 128;          // [128]

    int tid = threadIdx.x;
    int bh = blockIdx.y;
    int b = bh >> 3, h = bh & 7;
    int i0 = blockIdx.x * 128;
    const float* qb = g_qkv + ((size_t)b * 768 + h * 32) * 1024;
    const float* kb = qb + 256 * 1024;
    const float* vb = qb + 512 * 1024;

    #pragma unroll
    for (int t = 0; t < 4; t++) {
        int idx = tid + t * 256;
        int d = idx >> 5, c4 = (idx & 31) * 4;
        *(float4*)&Qs[d * 132 + c4] = *(const float4*)(qb + (size_t)d * 1024 + i0 + c4);
    }
    if (tid < 128) { smx[tid] = -1e30f; sl[tid] = 0.f; }

    const int rg = tid >> 4, cg = tid & 15;
    const int ri0 = rg * 8;
    const int rg2 = tid >> 3, cg2 = tid & 7;
    const int ri2 = rg2 * 4;

    u64 Oa[2][4] = {};   // (0,0) pairs

    for (int jt = 0; jt < 8; jt++) {
        int j0 = jt * 128;
        __syncthreads();
        #pragma unroll
        for (int t = 0; t < 4; t++) {
            int idx = tid + t * 256;
            int d = idx >> 5, c4 = (idx & 31) * 4;
            *(float4*)&Ks[d * 132 + c4] = *(const float4*)(kb + (size_t)d * 1024 + j0 + c4);
            *(float4*)&Vs[d * 132 + c4] = *(const float4*)(vb + (size_t)d * 1024 + j0 + c4);
        }
        __syncthreads();

        // --- QK^T ---
        u64 acc[4][8] = {};
        #pragma unroll
        for (int d = 0; d < 32; d++) {
            float4 q0 = *(float4*)&Qs[d * 132 + ri0];
            float4 q1 = *(float4*)&Qs[d * 132 + ri0 + 4];
            u64 qp[4] = { pk2(q0.x, q0.y), pk2(q0.z, q0.w),
                          pk2(q1.x, q1.y), pk2(q1.z, q1.w) };
            #pragma unroll
            for (int jj = 0; jj < 8; jj++) {
                float kv = Ks[d * 132 + cg + 16 * jj];
                u64 kp = pk2(kv, kv);
                fma2(acc[0][jj], qp[0], kp);
                fma2(acc[1][jj], qp[1], kp);
                fma2(acc[2][jj], qp[2], kp);
                fma2(acc[3][jj], qp[3], kp);
            }
        }
        float s[8][8];
        #pragma unroll
        for (int ip = 0; ip < 4; ip++)
            #pragma unroll
            for (int jj = 0; jj < 8; jj++)
                upk2(s[2 * ip][jj], s[2 * ip + 1][jj], acc[ip][jj]);

        // --- online softmax (raw-score domain, exp2 with folded scale) ---
        float mold[8], mnew[8], rsum[8];
        #pragma unroll
        for (int i = 0; i < 8; i++) {
            float mx = s[i][0];
            #pragma unroll
            for (int jj = 1; jj < 8; jj++) mx = fmaxf(mx, s[i][jj]);
            #pragma unroll
            for (int msk = 1; msk < 16; msk <<= 1)
                mx = fmaxf(mx, __shfl_xor_sync(0xffffffffu, mx, msk));
            mold[i] = smx[ri0 + i];
            mnew[i] = fmaxf(mold[i], mx);
        }
        #pragma unroll
        for (int i = 0; i < 8; i++) {
            float nk = -mnew[i] * KK2;
            float rs = 0.f;
            #pragma unroll
            for (int jj = 0; jj < 8; jj++) {
                float p = ex2(fmaf(s[i][jj], KK2, nk));
                s[i][jj] = p;
                rs += p;
            }
            #pragma unroll
            for (int msk = 1; msk < 16; msk <<= 1)
                rs += __shfl_xor_sync(0xffffffffu, rs, msk);
            rsum[i] = rs;
        }
        if (cg == 0) {
            #pragma unroll
            for (int i = 0; i < 8; i++) {
                float c = ex2((mold[i] - mnew[i]) * KK2);
                sc[ri0 + i] = c;
                smx[ri0 + i] = mnew[i];
                sl[ri0 + i] = sl[ri0 + i] * c + rsum[i];
            }
        }
        // store P j-major
        #pragma unroll
        for (int jj = 0; jj < 8; jj++) {
            int col = cg + 16 * jj;
            *(float4*)&Ps[col * 132 + ri0] =
                make_float4(s[0][jj], s[1][jj], s[2][jj], s[3][jj]);
            *(float4*)&Ps[col * 132 + ri0 + 4] =
                make_float4(s[4][jj], s[5][jj], s[6][jj], s[7][jj]);
        }
        __syncthreads();

        // --- P @ V ---
        u64 c01 = pk2(sc[ri2], sc[ri2 + 1]);
        u64 c23 = pk2(sc[ri2 + 2], sc[ri2 + 3]);
        #pragma unroll
        for (int w = 0; w < 4; w++) { mul2(Oa[0][w], c01); mul2(Oa[1][w], c23); }
        #pragma unroll 4
        for (int j = 0; j < 128; j++) {
            float4 p4 = *(float4*)&Ps[j * 132 + ri2];
            u64 p01 = pk2(p4.x, p4.y), p23 = pk2(p4.z, p4.w);
            float v0 = Vs[(cg2) * 132 + j];
            float v1 = Vs[(cg2 + 8) * 132 + j];
            float v2 = Vs[(cg2 + 16) * 132 + j];
            float v3 = Vs[(cg2 + 24) * 132 + j];
            u64 vb0 = pk2(v0, v0), vb1 = pk2(v1, v1);
            u64 vb2 = pk2(v2, v2), vb3 = pk2(v3, v3);
            fma2(Oa[0][0], p01, vb0); fma2(Oa[0][1], p01, vb1);
            fma2(Oa[0][2], p01, vb2); fma2(Oa[0][3], p01, vb3);
            fma2(Oa[1][0], p23, vb0); fma2(Oa[1][1], p23, vb1);
            fma2(Oa[1][2], p23, vb2); fma2(Oa[1][3], p23, vb3);
        }
    }
    __syncthreads();

    float li[4];
    #pragma unroll
    for (int u = 0; u < 4; u++) li[u] = 1.f / sl[ri2 + u];
    float* ob = g_att + ((size_t)b * 256 + h * 32) * 1024 + i0;
    #pragma unroll
    for (int up = 0; up < 2; up++)
        #pragma unroll
        for (int w = 0; w < 4; w++) {
            float lo, hi;
            upk2(lo, hi, Oa[up][w]);
            int d = cg2 + 8 * w;
            ob[(size_t)d * 1024 + ri2 + 2 * up]     = lo * li[2 * up];
            ob[(size_t)d * 1024 + ri2 + 2 * up + 1] = hi * li[2 * up + 1];
        }
}

// ---------------------------------------------------------------------------
extern "C" void kernel_launch(void* const* d_in, const int* in_sizes, int n_in,
                              void* d_out, int out_size) {
    const float* x      = (const float*)d_in[0];
    const float* gamma  = (const float*)d_in[1];
    const float* beta   = (const float*)d_in[2];
    const float* w_qkv  = (const float*)d_in[3];
    const float* w_proj = (const float*)d_in[4];
    const float* b_proj = (const float*)d_in[5];
    float* out = (float*)d_out;

    float* qkv; cudaGetSymbolAddress((void**)&qkv, g_qkv);
    float* att; cudaGetSymbolAddress((void**)&att, g_att);

    static int smem_set = 0;
    const int FLASH_SMEM = (3 * 32 * 132 + 128 * 132 + 3 * 128) * 4;
    if (!smem_set) {
        cudaFuncSetAttribute(flash_kernel,
                             cudaFuncAttributeMaxDynamicSharedMemorySize,
                             FLASH_SMEM);
        smem_set = 1;
    }

    // 1. GroupNorm stats -> affine coefficients
    gnstat_kernel<<<B_ * GROUPS_, 256>>>(x, gamma, beta);

    // 2. QKV GEMM with fused GN affine
    {
        dim3 grid(S_ / 128, (3 * C_) / 128, B_);
        gemm_f2<128, 8, false, true><<<grid, 256>>>(
            w_qkv, x, qkv, nullptr, nullptr, 3 * C_, C_);
    }

    // 3. Fused flash attention
    {
        dim3 grid(S_ / 128, B_ * HEADS_);
        flash_kernel<<<grid, 256, FLASH_SMEM>>>();
    }

    // 4. Proj + bias + residual
    {
        dim3 grid(S_ / 128, C_ / 64, B_);
        gemm_f2<64, 4, true, false><<<grid, 256>>>(
            w_proj, att, out, b_proj, x, C_, C_);
    }
}

// round 3
// speedup vs baseline: 1.3567x; 1.0004x over previous
#include <cuda_runtime.h>

#define B_    4
#define C_    256
#define S_    1024
#define HEADS_ 8
#define D_    32
#define GROUPS_ 32
#define CPG_  8
#define EPS_  1e-5f
#define SCALE_ 0.17677669529663687f
#define KK2   (SCALE_ * 1.4426950408889634f)   // scale * log2(e)

typedef unsigned long long u64;

// Scratch
__device__ float g_qkv[B_ * 3 * C_ * S_];   // [b][768][1024]
__device__ float g_att[B_ * C_ * S_];       // [b][256][1024]
__device__ float g_coefA[B_ * C_];
__device__ float g_coefB[B_ * C_];

// ---------------------------------------------------------------------------
// f32x2 helpers
// ---------------------------------------------------------------------------
__device__ __forceinline__ u64 pk2(float lo, float hi) {
    u64 r; asm("mov.b64 %0, {%1, %2};" : "=l"(r) : "f"(lo), "f"(hi)); return r;
}
__device__ __forceinline__ void upk2(float& lo, float& hi, u64 v) {
    asm("mov.b64 {%0, %1}, %2;" : "=f"(lo), "=f"(hi) : "l"(v));
}
__device__ __forceinline__ void fma2(u64& d, u64 a, u64 b) {
    asm("fma.rn.f32x2 %0, %1, %2, %0;" : "+l"(d) : "l"(a), "l"(b));
}
__device__ __forceinline__ void mul2(u64& d, u64 a) {
    asm("mul.rn.f32x2 %0, %1, %0;" : "+l"(d) : "l"(a));
}
__device__ __forceinline__ float ex2(float x) {
    float r; asm("ex2.approx.ftz.f32 %0, %1;" : "=f"(r) : "f"(x)); return r;
}

// ---------------------------------------------------------------------------
// GroupNorm stats -> per-channel affine coefficients (no normalized tensor)
// ---------------------------------------------------------------------------
__global__ __launch_bounds__(256) void gnstat_kernel(
    const float* __restrict__ x, const float* __restrict__ gamma,
    const float* __restrict__ beta) {
    int bg = blockIdx.x;
    int b = bg >> 5, g = bg & 31;
    const float4* x4 = (const float4*)(x + ((size_t)b * C_ + g * CPG_) * S_);
    int tid = threadIdx.x;
    float s0 = 0.f, s1 = 0.f;
    #pragma unroll
    for (int i = tid; i < 2048; i += 256) {
        float4 v = x4[i];
        s0 += v.x + v.y + v.z + v.w;
        s1 += v.x * v.x + v.y * v.y + v.z * v.z + v.w * v.w;
    }
    __shared__ float r0[256], r1[256];
    r0[tid] = s0; r1[tid] = s1;
    __syncthreads();
    for (int s = 128; s > 0; s >>= 1) {
        if (tid < s) { r0[tid] += r0[tid + s]; r1[tid] += r1[tid + s]; }
        __syncthreads();
    }
    if (tid < 8) {
        float m = r0[0] * (1.f / 8192.f);
        float var = r1[0] * (1.f / 8192.f) - m * m;
        float inv = rsqrtf(var + EPS_);
        int c = g * CPG_ + tid;
        float ga = gamma[c] * inv;
        g_coefA[b * C_ + c] = ga;
        g_coefB[b * C_ + c] = beta[c] - m * ga;
    }
}

// ---------------------------------------------------------------------------
// f32x2 GEMM: Out[b][m][n] = sum_k W[m][k] * X'[b][k][n]
// X' = AFFINE ? (X * coefA[k] + coefB[k]) : X.  PROJ adds bias + residual.
// BN = 128, BK = 16, 256 threads, microtile RM x 8 (as RM/2 x 4 f32x2 pairs).
// ---------------------------------------------------------------------------
template <int BM, int RM, bool PROJ, bool AFFINE>
__global__ __launch_bounds__(256) void gemm_f2(
    const float* __restrict__ W, const float* __restrict__ X,
    float* __restrict__ Out,
    const float* __restrict__ bias, const float* __restrict__ resid,
    int M, int K) {
    const int BK = 16;
    __shared__ float As[BK][BM + 4];
    __shared__ float Bs[BK][128];

    int b = blockIdx.z;
    int m0 = blockIdx.y * BM;
    int n0 = blockIdx.x * 128;
    const float* Xb = X + (size_t)b * K * S_;
    const float* cA = AFFINE ? (g_coefA + b * C_) : nullptr;
    const float* cB = AFFINE ? (g_coefB + b * C_) : nullptr;
    int tid = threadIdx.x;
    int rg = tid >> 4, cg = tid & 15;

    u64 acc[RM][4] = {};

    for (int k0 = 0; k0 < K; k0 += BK) {
        #pragma unroll
        for (int t = 0; t < BM / 64; t++) {
            int idx = tid + t * 256;
            int row = idx >> 2;
            int kq = (idx & 3) * 4;
            float4 v = *(const float4*)&W[(size_t)(m0 + row) * K + k0 + kq];
            As[kq + 0][row] = v.x; As[kq + 1][row] = v.y;
            As[kq + 2][row] = v.z; As[kq + 3][row] = v.w;
        }
        #pragma unroll
        for (int t = 0; t < 2; t++) {
            int idx = tid + t * 256;
            int row = idx >> 5;
            int n4 = (idx & 31) * 4;
            float4 v = *(const float4*)&Xb[(size_t)(k0 + row) * S_ + n0 + n4];
            if (AFFINE) {
                int c = k0 + row;
                float a = cA[c], be = cB[c];
                v.x = fmaf(v.x, a, be); v.y = fmaf(v.y, a, be);
                v.z = fmaf(v.z, a, be); v.w = fmaf(v.w, a, be);
            }
            *(float4*)&Bs[row][n4] = v;
        }
        __syncthreads();
        #pragma unroll
        for (int k = 0; k < BK; k++) {
            float4 b0 = *(float4*)&Bs[k][cg * 8];
            float4 b1 = *(float4*)&Bs[k][cg * 8 + 4];
            u64 bp[4] = { pk2(b0.x, b0.y), pk2(b0.z, b0.w),
                          pk2(b1.x, b1.y), pk2(b1.z, b1.w) };
            float a[RM];
            #pragma unroll
            for (int t = 0; t < RM / 4; t++) {
                float4 av = *(float4*)&As[k][rg * RM + t * 4];
                a[t * 4 + 0] = av.x; a[t * 4 + 1] = av.y;
                a[t * 4 + 2] = av.z; a[t * 4 + 3] = av.w;
            }
            #pragma unroll
            for (int i = 0; i < RM; i++) {
                u64 ab = pk2(a[i], a[i]);
                #pragma unroll
                for (int jp = 0; jp < 4; jp++) fma2(acc[i][jp], ab, bp[jp]);
            }
        }
        __syncthreads();
    }

    #pragma unroll
    for (int i = 0; i < RM; i++) {
        int m = m0 + rg * RM + i;
        float bia = PROJ ? bias[m] : 0.f;
        #pragma unroll
        for (int jp = 0; jp < 4; jp++) {
            float lo, hi;
            upk2(lo, hi, acc[i][jp]);
            int n = n0 + cg * 8 + jp * 2;
            size_t o = ((size_t)b * M + m) * S_ + n;
            lo += bia; hi += bia;
            if (PROJ) { lo += resid[o]; hi += resid[o + 1]; }
            Out[o] = lo; Out[o + 1] = hi;
        }
    }
}

// ---------------------------------------------------------------------------
// Fused flash attention. Block = (bh, 128-query tile). 256 threads.
// Smem: Qs/Ks/Vs [32][132] d-major; Ps [128 j][132] j-major; row stats.
// QK microtile: rows rg*8..+7 (pairs), cols cg + 16*jj (jj<8).
// PV microtile: rows rg2*4..+3 (pairs), cols d = cg2 + 8*w (w<4).
// ---------------------------------------------------------------------------
__global__ __launch_bounds__(256) void flash_kernel() {
    extern __shared__ float sh[];
    float* Qs = sh;                 // 32*132
    float* Ks = Qs + 32 * 132;
    float* Vs = Ks + 32 * 132;
    float* Ps = Vs + 32 * 132;      // 128*132
    float* smx = Ps + 128 * 132;    // [128]
    float* sl  = smx + 128;         // [128]
    float* sc  = sl + 128;          // [128]

    int tid = threadIdx.x;
    int bh = blockIdx.y;
    int b = bh >> 3, h = bh & 7;
    int i0 = blockIdx.x * 128;
    const float* qb = g_qkv + ((size_t)b * 768 + h * 32) * 1024;
    const float* kb = qb + 256 * 1024;
    const float* vb = qb + 512 * 1024;

    #pragma unroll
    for (int t = 0; t < 4; t++) {
        int idx = tid + t * 256;
        int d = idx >> 5, c4 = (idx & 31) * 4;
        *(float4*)&Qs[d * 132 + c4] = *(const float4*)(qb + (size_t)d * 1024 + i0 + c4);
    }
    if (tid < 128) { smx[tid] = -1e30f; sl[tid] = 0.f; }

    const int rg = tid >> 4, cg = tid & 15;
    const int ri0 = rg * 8;
    const int rg2 = tid >> 3, cg2 = tid & 7;
    const int ri2 = rg2 * 4;

    u64 Oa[2][4] = {};   // (0,0) pairs

    for (int jt = 0; jt < 8; jt++) {
        int j0 = jt * 128;
        __syncthreads();
        #pragma unroll
        for (int t = 0; t < 4; t++) {
            int idx = tid + t * 256;
            int d = idx >> 5, c4 = (idx & 31) * 4;
            *(float4*)&Ks[d * 132 + c4] = *(const float4*)(kb + (size_t)d * 1024 + j0 + c4);
            *(float4*)&Vs[d * 132 + c4] = *(const float4*)(vb + (size_t)d * 1024 + j0 + c4);
        }
        __syncthreads();

        // --- QK^T ---
        u64 acc[4][8] = {};
        #pragma unroll
        for (int d = 0; d < 32; d++) {
            float4 q0 = *(float4*)&Qs[d * 132 + ri0];
            float4 q1 = *(float4*)&Qs[d * 132 + ri0 + 4];
            u64 qp[4] = { pk2(q0.x, q0.y), pk2(q0.z, q0.w),
                          pk2(q1.x, q1.y), pk2(q1.z, q1.w) };
            #pragma unroll
            for (int jj = 0; jj < 8; jj++) {
                float kv = Ks[d * 132 + cg + 16 * jj];
                u64 kp = pk2(kv, kv);
                fma2(acc[0][jj], qp[0], kp);
                fma2(acc[1][jj], qp[1], kp);
                fma2(acc[2][jj], qp[2], kp);
                fma2(acc[3][jj], qp[3], kp);
            }
        }
        float s[8][8];
        #pragma unroll
        for (int ip = 0; ip < 4; ip++)
            #pragma unroll
            for (int jj = 0; jj < 8; jj++)
                upk2(s[2 * ip][jj], s[2 * ip + 1][jj], acc[ip][jj]);

        // --- online softmax (raw-score domain, exp2 with folded scale) ---
        float mold[8], mnew[8], rsum[8];
        #pragma unroll
        for (int i = 0; i < 8; i++) {
            float mx = s[i][0];
            #pragma unroll
            for (int jj = 1; jj < 8; jj++) mx = fmaxf(mx, s[i][jj]);
            #pragma unroll
            for (int msk = 1; msk < 16; msk <<= 1)
                mx = fmaxf(mx, __shfl_xor_sync(0xffffffffu, mx, msk));
            mold[i] = smx[ri0 + i];
            mnew[i] = fmaxf(mold[i], mx);
        }
        #pragma unroll
        for (int i = 0; i < 8; i++) {
            float nk = -mnew[i] * KK2;
            float rs = 0.f;
            #pragma unroll
            for (int jj = 0; jj < 8; jj++) {
                float p = ex2(fmaf(s[i][jj], KK2, nk));
                s[i][jj] = p;
                rs += p;
            }
            #pragma unroll
            for (int msk = 1; msk < 16; msk <<= 1)
                rs += __shfl_xor_sync(0xffffffffu, rs, msk);
            rsum[i] = rs;
        }
        if (cg == 0) {
            #pragma unroll
            for (int i = 0; i < 8; i++) {
                float c = ex2((mold[i] - mnew[i]) * KK2);
                sc[ri0 + i] = c;
                smx[ri0 + i] = mnew[i];
                sl[ri0 + i] = sl[ri0 + i] * c + rsum[i];
            }
        }
        // store P j-major
        #pragma unroll
        for (int jj = 0; jj < 8; jj++) {
            int col = cg + 16 * jj;
            *(float4*)&Ps[col * 132 + ri0] =
                make_float4(s[0][jj], s[1][jj], s[2][jj], s[3][jj]);
            *(float4*)&Ps[col * 132 + ri0 + 4] =
                make_float4(s[4][jj], s[5][jj], s[6][jj], s[7][jj]);
        }
        __syncthreads();

        // --- P @ V ---
        u64 c01 = pk2(sc[ri2], sc[ri2 + 1]);
        u64 c23 = pk2(sc[ri2 + 2], sc[ri2 + 3]);
        #pragma unroll
        for (int w = 0; w < 4; w++) { mul2(Oa[0][w], c01); mul2(Oa[1][w], c23); }
        #pragma unroll 4
        for (int j = 0; j < 128; j++) {
            float4 p4 = *(float4*)&Ps[j * 132 + ri2];
            u64 p01 = pk2(p4.x, p4.y), p23 = pk2(p4.z, p4.w);
            float v0 = Vs[(cg2) * 132 + j];
            float v1 = Vs[(cg2 + 8) * 132 + j];
            float v2 = Vs[(cg2 + 16) * 132 + j];
            float v3 = Vs[(cg2 + 24) * 132 + j];
            u64 vb0 = pk2(v0, v0), vb1 = pk2(v1, v1);
            u64 vb2 = pk2(v2, v2), vb3 = pk2(v3, v3);
            fma2(Oa[0][0], p01, vb0); fma2(Oa[0][1], p01, vb1);
            fma2(Oa[0][2], p01, vb2); fma2(Oa[0][3], p01, vb3);
            fma2(Oa[1][0], p23, vb0); fma2(Oa[1][1], p23, vb1);
            fma2(Oa[1][2], p23, vb2); fma2(Oa[1][3], p23, vb3);
        }
    }
    __syncthreads();

    float li[4];
    #pragma unroll
    for (int u = 0; u < 4; u++) li[u] = 1.f / sl[ri2 + u];
    float* ob = g_att + ((size_t)b * 256 + h * 32) * 1024 + i0;
    #pragma unroll
    for (int up = 0; up < 2; up++)
        #pragma unroll
        for (int w = 0; w < 4; w++) {
            float lo, hi;
            upk2(lo, hi, Oa[up][w]);
            int d = cg2 + 8 * w;
            ob[(size_t)d * 1024 + ri2 + 2 * up]     = lo * li[2 * up];
            ob[(size_t)d * 1024 + ri2 + 2 * up + 1] = hi * li[2 * up + 1];
        }
}

// ---------------------------------------------------------------------------
extern "C" void kernel_launch(void* const* d_in, const int* in_sizes, int n_in,
                              void* d_out, int out_size) {
    const float* x      = (const float*)d_in[0];
    const float* gamma  = (const float*)d_in[1];
    const float* beta   = (const float*)d_in[2];
    const float* w_qkv  = (const float*)d_in[3];
    const float* w_proj = (const float*)d_in[4];
    const float* b_proj = (const float*)d_in[5];
    float* out = (float*)d_out;

    float* qkv; cudaGetSymbolAddress((void**)&qkv, g_qkv);
    float* att; cudaGetSymbolAddress((void**)&att, g_att);

    static int smem_set = 0;
    const int FLASH_SMEM = (3 * 32 * 132 + 128 * 132 + 3 * 128) * 4;
    if (!smem_set) {
        cudaFuncSetAttribute(flash_kernel,
                             cudaFuncAttributeMaxDynamicSharedMemorySize,
                             FLASH_SMEM);
        smem_set = 1;
    }

    // 1. GroupNorm stats -> affine coefficients
    gnstat_kernel<<<B_ * GROUPS_, 256>>>(x, gamma, beta);

    // 2. QKV GEMM with fused GN affine
    {
        dim3 grid(S_ / 128, (3 * C_) / 128, B_);
        gemm_f2<128, 8, false, true><<<grid, 256>>>(
            w_qkv, x, qkv, nullptr, nullptr, 3 * C_, C_);
    }

    // 3. Fused flash attention
    {
        dim3 grid(S_ / 128, B_ * HEADS_);
        flash_kernel<<<grid, 256, FLASH_SMEM>>>();
    }

    // 4. Proj + bias + residual
    {
        dim3 grid(S_ / 128, C_ / 64, B_);
        gemm_f2<64, 4, true, false><<<grid, 256>>>(
            w_proj, att, out, b_proj, x, C_, C_);
    }
}

// round 4
// speedup vs baseline: 1.6137x; 1.1894x over previous
#include <cuda_runtime.h>

#define B_    4
#define C_    256
#define S_    1024
#define HEADS_ 8
#define D_    32
#define EPS_  1e-5f
#define KK2   0.2550635236562097f   // (1/sqrt(32)) * log2(e)

typedef unsigned long long u64;

// Scratch
__device__ float g_qkv[B_ * 3 * C_ * S_];   // [b][768][1024]
__device__ float g_att[B_ * C_ * S_];       // [b][256][1024]
__device__ float g_coefA[B_ * C_];
__device__ float g_coefB[B_ * C_];

// ---------------------------------------------------------------------------
// f32x2 helpers
// ---------------------------------------------------------------------------
__device__ __forceinline__ u64 pk2(float lo, float hi) {
    u64 r; asm("mov.b64 %0, {%1, %2};" : "=l"(r) : "f"(lo), "f"(hi)); return r;
}
__device__ __forceinline__ void upk2(float& lo, float& hi, u64 v) {
    asm("mov.b64 {%0, %1}, %2;" : "=f"(lo), "=f"(hi) : "l"(v));
}
__device__ __forceinline__ void fma2(u64& d, u64 a, u64 b) {
    asm("fma.rn.f32x2 %0, %1, %2, %0;" : "+l"(d) : "l"(a), "l"(b));
}
__device__ __forceinline__ void mul2(u64& d, u64 a) {
    asm("mul.rn.f32x2 %0, %1, %0;" : "+l"(d) : "l"(a));
}
__device__ __forceinline__ float ex2(float x) {
    float r; asm("ex2.approx.ftz.f32 %0, %1;" : "=f"(r) : "f"(x)); return r;
}

// ---------------------------------------------------------------------------
// GroupNorm stats -> per-channel affine coefficients
// ---------------------------------------------------------------------------
__global__ __launch_bounds__(256) void gnstat_kernel(
    const float* __restrict__ x, const float* __restrict__ gamma,
    const float* __restrict__ beta) {
    int bg = blockIdx.x;
    int b = bg >> 5, g = bg & 31;
    const float4* x4 = (const float4*)(x + ((size_t)b * C_ + g * 8) * S_);
    int tid = threadIdx.x;
    float s0 = 0.f, s1 = 0.f;
    #pragma unroll
    for (int i = tid; i < 2048; i += 256) {
        float4 v = x4[i];
        s0 += v.x + v.y + v.z + v.w;
        s1 += v.x * v.x + v.y * v.y + v.z * v.z + v.w * v.w;
    }
    __shared__ float r0[256], r1[256];
    r0[tid] = s0; r1[tid] = s1;
    __syncthreads();
    for (int s = 128; s > 0; s >>= 1) {
        if (tid < s) { r0[tid] += r0[tid + s]; r1[tid] += r1[tid + s]; }
        __syncthreads();
    }
    if (tid < 8) {
        float m = r0[0] * (1.f / 8192.f);
        float var = r1[0] * (1.f / 8192.f) - m * m;
        float inv = rsqrtf(var + EPS_);
        int c = g * 8 + tid;
        float ga = gamma[c] * inv;
        g_coefA[b * C_ + c] = ga;
        g_coefB[b * C_ + c] = beta[c] - m * ga;
    }
}

// ---------------------------------------------------------------------------
// f32x2 GEMM with register-prefetch double buffering. BN = 64, BK = 16.
// Out[b][m][n] = sum_k W[m][k] * X'[b][k][n]
// X' = AFFINE ? (X * coefA[k] + coefB[k]) : X.  PROJ adds bias + residual.
// 256 threads: microtile RM rows x 4 cols.
// ---------------------------------------------------------------------------
template <int BM, int RM, bool PROJ, bool AFFINE>
__global__ __launch_bounds__(256, 2) void gemm_f2(
    const float* __restrict__ W, const float* __restrict__ X,
    float* __restrict__ Out,
    const float* __restrict__ bias, const float* __restrict__ resid,
    int M, int K) {
    __shared__ float As[16][BM + 4];
    __shared__ float Bs[16][64];
    const int NA = BM / 64;      // A-tile float4 loads per thread

    int b = blockIdx.z;
    int m0 = blockIdx.y * BM;
    int n0 = blockIdx.x * 64;
    const float* Xb = X + (size_t)b * K * S_;
    const float* cA = AFFINE ? (g_coefA + b * C_) : nullptr;
    const float* cB = AFFINE ? (g_coefB + b * C_) : nullptr;
    int tid = threadIdx.x;
    int rg = tid >> 4, cg = tid & 15;
    int brow = tid >> 4, bn4 = (tid & 15) * 4;   // B tile: 16 rows x 16 float4

    // Prefetch chunk 0 into registers
    float4 pa[NA], pb;
    #pragma unroll
    for (int t = 0; t < NA; t++) {
        int idx = tid + t * 256;
        int row = idx >> 2, kq = (idx & 3) * 4;
        pa[t] = *(const float4*)&W[(size_t)(m0 + row) * K + kq];
    }
    pb = *(const float4*)&Xb[(size_t)brow * S_ + n0 + bn4];

    u64 acc[RM][2] = {};
    const int NCH = K / 16;

    for (int ch = 0; ch < NCH; ch++) {
        // Commit prefetched chunk to smem
        #pragma unroll
        for (int t = 0; t < NA; t++) {
            int idx = tid + t * 256;
            int row = idx >> 2, kq = (idx & 3) * 4;
            As[kq + 0][row] = pa[t].x; As[kq + 1][row] = pa[t].y;
            As[kq + 2][row] = pa[t].z; As[kq + 3][row] = pa[t].w;
        }
        {
            float4 v = pb;
            if (AFFINE) {
                int c = ch * 16 + brow;
                float a = cA[c], be = cB[c];
                v.x = fmaf(v.x, a, be); v.y = fmaf(v.y, a, be);
                v.z = fmaf(v.z, a, be); v.w = fmaf(v.w, a, be);
            }
            *(float4*)&Bs[brow][bn4] = v;
        }
        __syncthreads();

        // Prefetch next chunk (global loads overlap with FMA burst below)
        if (ch + 1 < NCH) {
            #pragma unroll
            for (int t = 0; t < NA; t++) {
                int idx = tid + t * 256;
                int row = idx >> 2, kq = (idx & 3) * 4;
                pa[t] = *(const float4*)&W[(size_t)(m0 + row) * K + (ch + 1) * 16 + kq];
            }
            pb = *(const float4*)&Xb[(size_t)((ch + 1) * 16 + brow) * S_ + n0 + bn4];
        }

        #pragma unroll
        for (int k = 0; k < 16; k++) {
            float4 bv = *(float4*)&Bs[k][cg * 4];
            u64 bp0 = pk2(bv.x, bv.y), bp1 = pk2(bv.z, bv.w);
            float a[RM];
            #pragma unroll
            for (int t = 0; t < RM / 4; t++) {
                float4 av = *(float4*)&As[k][rg * RM + t * 4];
                a[t * 4 + 0] = av.x; a[t * 4 + 1] = av.y;
                a[t * 4 + 2] = av.z; a[t * 4 + 3] = av.w;
            }
            #pragma unroll
            for (int i = 0; i < RM; i++) {
                u64 ab = pk2(a[i], a[i]);
                fma2(acc[i][0], ab, bp0);
                fma2(acc[i][1], ab, bp1);
            }
        }
        __syncthreads();
    }

    #pragma unroll
    for (int i = 0; i < RM; i++) {
        int m = m0 + rg * RM + i;
        float bia = PROJ ? bias[m] : 0.f;
        #pragma unroll
        for (int jp = 0; jp < 2; jp++) {
            float lo, hi;
            upk2(lo, hi, acc[i][jp]);
            int n = n0 + cg * 4 + jp * 2;
            size_t o = ((size_t)b * M + m) * S_ + n;
            lo += bia; hi += bia;
            if (PROJ) { lo += resid[o]; hi += resid[o + 1]; }
            Out[o] = lo; Out[o + 1] = hi;
        }
    }
}

// ---------------------------------------------------------------------------
// Fused flash attention (unchanged from passing version).
// Block = (bh, 128-query tile). 256 threads.
// ---------------------------------------------------------------------------
__global__ __launch_bounds__(256) void flash_kernel() {
    extern __shared__ float sh[];
    float* Qs = sh;                 // 32*132
    float* Ks = Qs + 32 * 132;
    float* Vs = Ks + 32 * 132;
    float* Ps = Vs + 32 * 132;      // 128*132
    float* smx = Ps + 128 * 132;    // [128]
    float* sl  = smx + 128;         // [128]
    float* sc  = sl + 128;          // [128]

    int tid = threadIdx.x;
    int bh = blockIdx.y;
    int b = bh >> 3, h = bh & 7;
    int i0 = blockIdx.x * 128;
    const float* qb = g_qkv + ((size_t)b * 768 + h * 32) * 1024;
    const float* kb = qb + 256 * 1024;
    const float* vb = qb + 512 * 1024;

    #pragma unroll
    for (int t = 0; t < 4; t++) {
        int idx = tid + t * 256;
        int d = idx >> 5, c4 = (idx & 31) * 4;
        *(float4*)&Qs[d * 132 + c4] = *(const float4*)(qb + (size_t)d * 1024 + i0 + c4);
    }
    if (tid < 128) { smx[tid] = -1e30f; sl[tid] = 0.f; }

    const int rg = tid >> 4, cg = tid & 15;
    const int ri0 = rg * 8;
    const int rg2 = tid >> 3, cg2 = tid & 7;
    const int ri2 = rg2 * 4;

    u64 Oa[2][4] = {};

    for (int jt = 0; jt < 8; jt++) {
        int j0 = jt * 128;
        __syncthreads();
        #pragma unroll
        for (int t = 0; t < 4; t++) {
            int idx = tid + t * 256;
            int d = idx >> 5, c4 = (idx & 31) * 4;
            *(float4*)&Ks[d * 132 + c4] = *(const float4*)(kb + (size_t)d * 1024 + j0 + c4);
            *(float4*)&Vs[d * 132 + c4] = *(const float4*)(vb + (size_t)d * 1024 + j0 + c4);
        }
        __syncthreads();

        // --- QK^T ---
        u64 acc[4][8] = {};
        #pragma unroll
        for (int d = 0; d < 32; d++) {
            float4 q0 = *(float4*)&Qs[d * 132 + ri0];
            float4 q1 = *(float4*)&Qs[d * 132 + ri0 + 4];
            u64 qp[4] = { pk2(q0.x, q0.y), pk2(q0.z, q0.w),
                          pk2(q1.x, q1.y), pk2(q1.z, q1.w) };
            #pragma unroll
            for (int jj = 0; jj < 8; jj++) {
                float kv = Ks[d * 132 + cg + 16 * jj];
                u64 kp = pk2(kv, kv);
                fma2(acc[0][jj], qp[0], kp);
                fma2(acc[1][jj], qp[1], kp);
                fma2(acc[2][jj], qp[2], kp);
                fma2(acc[3][jj], qp[3], kp);
            }
        }
        float s[8][8];
        #pragma unroll
        for (int ip = 0; ip < 4; ip++)
            #pragma unroll
            for (int jj = 0; jj < 8; jj++)
                upk2(s[2 * ip][jj], s[2 * ip + 1][jj], acc[ip][jj]);

        // --- online softmax ---
        float mold[8], mnew[8], rsum[8];
        #pragma unroll
        for (int i = 0; i < 8; i++) {
            float mx = s[i][0];
            #pragma unroll
            for (int jj = 1; jj < 8; jj++) mx = fmaxf(mx, s[i][jj]);
            #pragma unroll
            for (int msk = 1; msk < 16; msk <<= 1)
                mx = fmaxf(mx, __shfl_xor_sync(0xffffffffu, mx, msk));
            mold[i] = smx[ri0 + i];
            mnew[i] = fmaxf(mold[i], mx);
        }
        #pragma unroll
        for (int i = 0; i < 8; i++) {
            float nk = -mnew[i] * KK2;
            float rs = 0.f;
            #pragma unroll
            for (int jj = 0; jj < 8; jj++) {
                float p = ex2(fmaf(s[i][jj], KK2, nk));
                s[i][jj] = p;
                rs += p;
            }
            #pragma unroll
            for (int msk = 1; msk < 16; msk <<= 1)
                rs += __shfl_xor_sync(0xffffffffu, rs, msk);
            rsum[i] = rs;
        }
        if (cg == 0) {
            #pragma unroll
            for (int i = 0; i < 8; i++) {
                float c = ex2((mold[i] - mnew[i]) * KK2);
                sc[ri0 + i] = c;
                smx[ri0 + i] = mnew[i];
                sl[ri0 + i] = sl[ri0 + i] * c + rsum[i];
            }
        }
        #pragma unroll
        for (int jj = 0; jj < 8; jj++) {
            int col = cg + 16 * jj;
            *(float4*)&Ps[col * 132 + ri0] =
                make_float4(s[0][jj], s[1][jj], s[2][jj], s[3][jj]);
            *(float4*)&Ps[col * 132 + ri0 + 4] =
                make_float4(s[4][jj], s[5][jj], s[6][jj], s[7][jj]);
        }
        __syncthreads();

        // --- P @ V ---
        u64 c01 = pk2(sc[ri2], sc[ri2 + 1]);
        u64 c23 = pk2(sc[ri2 + 2], sc[ri2 + 3]);
        #pragma unroll
        for (int w = 0; w < 4; w++) { mul2(Oa[0][w], c01); mul2(Oa[1][w], c23); }
        #pragma unroll 4
        for (int j = 0; j < 128; j++) {
            float4 p4 = *(float4*)&Ps[j * 132 + ri2];
            u64 p01 = pk2(p4.x, p4.y), p23 = pk2(p4.z, p4.w);
            float v0 = Vs[(cg2) * 132 + j];
            float v1 = Vs[(cg2 + 8) * 132 + j];
            float v2 = Vs[(cg2 + 16) * 132 + j];
            float v3 = Vs[(cg2 + 24) * 132 + j];
            u64 vb0 = pk2(v0, v0), vb1 = pk2(v1, v1);
            u64 vb2 = pk2(v2, v2), vb3 = pk2(v3, v3);
            fma2(Oa[0][0], p01, vb0); fma2(Oa[0][1], p01, vb1);
            fma2(Oa[0][2], p01, vb2); fma2(Oa[0][3], p01, vb3);
            fma2(Oa[1][0], p23, vb0); fma2(Oa[1][1], p23, vb1);
            fma2(Oa[1][2], p23, vb2); fma2(Oa[1][3], p23, vb3);
        }
    }
    __syncthreads();

    float li[4];
    #pragma unroll
    for (int u = 0; u < 4; u++) li[u] = 1.f / sl[ri2 + u];
    float* ob = g_att + ((size_t)b * 256 + h * 32) * 1024 + i0;
    #pragma unroll
    for (int up = 0; up < 2; up++)
        #pragma unroll
        for (int w = 0; w < 4; w++) {
            float lo, hi;
            upk2(lo, hi, Oa[up][w]);
            int d = cg2 + 8 * w;
            ob[(size_t)d * 1024 + ri2 + 2 * up]     = lo * li[2 * up];
            ob[(size_t)d * 1024 + ri2 + 2 * up + 1] = hi * li[2 * up + 1];
        }
}

// ---------------------------------------------------------------------------
extern "C" void kernel_launch(void* const* d_in, const int* in_sizes, int n_in,
                              void* d_out, int out_size) {
    const float* x      = (const float*)d_in[0];
    const float* gamma  = (const float*)d_in[1];
    const float* beta   = (const float*)d_in[2];
    const float* w_qkv  = (const float*)d_in[3];
    const float* w_proj = (const float*)d_in[4];
    const float* b_proj = (const float*)d_in[5];
    float* out = (float*)d_out;

    float* qkv; cudaGetSymbolAddress((void**)&qkv, g_qkv);
    float* att; cudaGetSymbolAddress((void**)&att, g_att);

    static int smem_set = 0;
    const int FLASH_SMEM = (3 * 32 * 132 + 128 * 132 + 3 * 128) * 4;
    if (!smem_set) {
        cudaFuncSetAttribute(flash_kernel,
                             cudaFuncAttributeMaxDynamicSharedMemorySize,
                             FLASH_SMEM);
        smem_set = 1;
    }

    // 1. GroupNorm stats -> affine coefficients
    gnstat_kernel<<<B_ * 32, 256>>>(x, gamma, beta);

    // 2. QKV GEMM with fused GN affine: grid 16 x 6 x 4 = 384 blocks
    {
        dim3 grid(S_ / 64, (3 * C_) / 128, B_);
        gemm_f2<128, 8, false, true><<<grid, 256>>>(
            w_qkv, x, qkv, nullptr, nullptr, 3 * C_, C_);
    }

    // 3. Fused flash attention
    {
        dim3 grid(S_ / 128, B_ * HEADS_);
        flash_kernel<<<grid, 256, FLASH_SMEM>>>();
    }

    // 4. Proj + bias + residual: grid 16 x 4 x 4 = 256 blocks
    {
        dim3 grid(S_ / 64, C_ / 64, B_);
        gemm_f2<64, 4, true, false><<<grid, 256>>>(
            w_proj, att, out, b_proj, x, C_, C_);
    }
}

// round 5
// speedup vs baseline: 1.6807x; 1.0415x over previous
#include <cuda_runtime.h>

#define B_    4
#define C_    256
#define S_    1024
#define HEADS_ 8
#define D_    32
#define EPS_  1e-5f
#define KK2   0.2550635236562097f   // (1/sqrt(32)) * log2(e)

typedef unsigned long long u64;

// Scratch
__device__ float g_qkv[B_ * 3 * C_ * S_];       // [b][768][1024] (Q,K used)
__device__ float g_vt[B_ * HEADS_ * S_ * D_];   // [bh][s][d]  (V transposed)
__device__ float g_att[B_ * C_ * S_];           // [b][256][1024]
__device__ float g_coefA[B_ * C_];
__device__ float g_coefB[B_ * C_];

// ---------------------------------------------------------------------------
// f32x2 helpers
// ---------------------------------------------------------------------------
__device__ __forceinline__ u64 pk2(float lo, float hi) {
    u64 r; asm("mov.b64 %0, {%1, %2};" : "=l"(r) : "f"(lo), "f"(hi)); return r;
}
__device__ __forceinline__ void upk2(float& lo, float& hi, u64 v) {
    asm("mov.b64 {%0, %1}, %2;" : "=f"(lo), "=f"(hi) : "l"(v));
}
__device__ __forceinline__ void fma2(u64& d, u64 a, u64 b) {
    asm("fma.rn.f32x2 %0, %1, %2, %0;" : "+l"(d) : "l"(a), "l"(b));
}
__device__ __forceinline__ void mul2(u64& d, u64 a) {
    asm("mul.rn.f32x2 %0, %1, %0;" : "+l"(d) : "l"(a));
}
__device__ __forceinline__ float ex2(float x) {
    float r; asm("ex2.approx.ftz.f32 %0, %1;" : "=f"(r) : "f"(x)); return r;
}

// ---------------------------------------------------------------------------
// GroupNorm stats -> per-channel affine coefficients
// ---------------------------------------------------------------------------
__global__ __launch_bounds__(256) void gnstat_kernel(
    const float* __restrict__ x, const float* __restrict__ gamma,
    const float* __restrict__ beta) {
    int bg = blockIdx.x;
    int b = bg >> 5, g = bg & 31;
    const float4* x4 = (const float4*)(x + ((size_t)b * C_ + g * 8) * S_);
    int tid = threadIdx.x;
    float s0 = 0.f, s1 = 0.f;
    #pragma unroll
    for (int i = tid; i < 2048; i += 256) {
        float4 v = x4[i];
        s0 += v.x + v.y + v.z + v.w;
        s1 += v.x * v.x + v.y * v.y + v.z * v.z + v.w * v.w;
    }
    __shared__ float r0[256], r1[256];
    r0[tid] = s0; r1[tid] = s1;
    __syncthreads();
    for (int s = 128; s > 0; s >>= 1) {
        if (tid < s) { r0[tid] += r0[tid + s]; r1[tid] += r1[tid + s]; }
        __syncthreads();
    }
    if (tid < 8) {
        float m = r0[0] * (1.f / 8192.f);
        float var = r1[0] * (1.f / 8192.f) - m * m;
        float inv = rsqrtf(var + EPS_);
        int c = g * 8 + tid;
        float ga = gamma[c] * inv;
        g_coefA[b * C_ + c] = ga;
        g_coefB[b * C_ + c] = beta[c] - m * ga;
    }
}

// ---------------------------------------------------------------------------
// f32x2 GEMM, register-prefetch double buffer. BN=64, BK=16, 256 threads.
// VT: rows m>=512 (the V third of QKV) are written transposed to g_vt[bh][s][d].
// ---------------------------------------------------------------------------
template <int BM, int RM, bool PROJ, bool AFFINE, bool VT>
__global__ __launch_bounds__(256, 2) void gemm_f2(
    const float* __restrict__ W, const float* __restrict__ X,
    float* __restrict__ Out,
    const float* __restrict__ bias, const float* __restrict__ resid,
    int M, int K) {
    __shared__ float As[16][BM + 4];
    __shared__ float Bs[16][64];
    const int NA = BM / 64;

    int b = blockIdx.z;
    int m0 = blockIdx.y * BM;
    int n0 = blockIdx.x * 64;
    const float* Xb = X + (size_t)b * K * S_;
    const float* cA = AFFINE ? (g_coefA + b * C_) : nullptr;
    const float* cB = AFFINE ? (g_coefB + b * C_) : nullptr;
    int tid = threadIdx.x;
    int rg = tid >> 4, cg = tid & 15;
    int brow = tid >> 4, bn4 = (tid & 15) * 4;

    float4 pa[NA], pb;
    #pragma unroll
    for (int t = 0; t < NA; t++) {
        int idx = tid + t * 256;
        int row = idx >> 2, kq = (idx & 3) * 4;
        pa[t] = *(const float4*)&W[(size_t)(m0 + row) * K + kq];
    }
    pb = *(const float4*)&Xb[(size_t)brow * S_ + n0 + bn4];

    u64 acc[RM][2] = {};
    const int NCH = K / 16;

    for (int ch = 0; ch < NCH; ch++) {
        #pragma unroll
        for (int t = 0; t < NA; t++) {
            int idx = tid + t * 256;
            int row = idx >> 2, kq = (idx & 3) * 4;
            As[kq + 0][row] = pa[t].x; As[kq + 1][row] = pa[t].y;
            As[kq + 2][row] = pa[t].z; As[kq + 3][row] = pa[t].w;
        }
        {
            float4 v = pb;
            if (AFFINE) {
                int c = ch * 16 + brow;
                float a = cA[c], be = cB[c];
                v.x = fmaf(v.x, a, be); v.y = fmaf(v.y, a, be);
                v.z = fmaf(v.z, a, be); v.w = fmaf(v.w, a, be);
            }
            *(float4*)&Bs[brow][bn4] = v;
        }
        __syncthreads();
        if (ch + 1 < NCH) {
            #pragma unroll
            for (int t = 0; t < NA; t++) {
                int idx = tid + t * 256;
                int row = idx >> 2, kq = (idx & 3) * 4;
                pa[t] = *(const float4*)&W[(size_t)(m0 + row) * K + (ch + 1) * 16 + kq];
            }
            pb = *(const float4*)&Xb[(size_t)((ch + 1) * 16 + brow) * S_ + n0 + bn4];
        }
        #pragma unroll
        for (int k = 0; k < 16; k++) {
            float4 bv = *(float4*)&Bs[k][cg * 4];
            u64 bp0 = pk2(bv.x, bv.y), bp1 = pk2(bv.z, bv.w);
            float a[RM];
            #pragma unroll
            for (int t = 0; t < RM / 4; t++) {
                float4 av = *(float4*)&As[k][rg * RM + t * 4];
                a[t * 4 + 0] = av.x; a[t * 4 + 1] = av.y;
                a[t * 4 + 2] = av.z; a[t * 4 + 3] = av.w;
            }
            #pragma unroll
            for (int i = 0; i < RM; i++) {
                u64 ab = pk2(a[i], a[i]);
                fma2(acc[i][0], ab, bp0);
                fma2(acc[i][1], ab, bp1);
            }
        }
        __syncthreads();
    }

    if constexpr (VT) {
        if (m0 >= 512) {
            // V rows: write transposed to g_vt[bh][s][d]
            float o[RM][4];
            #pragma unroll
            for (int i = 0; i < RM; i++) {
                upk2(o[i][0], o[i][1], acc[i][0]);
                upk2(o[i][2], o[i][3], acc[i][1]);
            }
            int mb = m0 - 512 + rg * RM;        // 0..255
            int h = mb >> 5, db = mb & 31;      // db multiple of 8
            float* vdst = g_vt + (size_t)(b * 8 + h) * 1024 * 32;
            #pragma unroll
            for (int u = 0; u < 4; u++) {
                int s = n0 + cg * 4 + u;
                *(float4*)&vdst[(size_t)s * 32 + db] =
                    make_float4(o[0][u], o[1][u], o[2][u], o[3][u]);
                *(float4*)&vdst[(size_t)s * 32 + db + 4] =
                    make_float4(o[4][u], o[5][u], o[6][u], o[7][u]);
            }
            return;
        }
    }

    #pragma unroll
    for (int i = 0; i < RM; i++) {
        int m = m0 + rg * RM + i;
        float bia = PROJ ? bias[m] : 0.f;
        #pragma unroll
        for (int jp = 0; jp < 2; jp++) {
            float lo, hi;
            upk2(lo, hi, acc[i][jp]);
            int n = n0 + cg * 4 + jp * 2;
            size_t o = ((size_t)b * M + m) * S_ + n;
            lo += bia; hi += bia;
            if (PROJ) { lo += resid[o]; hi += resid[o + 1]; }
            Out[o] = lo; Out[o + 1] = hi;
        }
    }
}

// ---------------------------------------------------------------------------
// Fused flash attention. 512 threads, BQ=128, K-tile 128, double-buffered K/V.
// QK microtile: 4i (2 pairs) x 8j.  PV: 4i x 4d (d-pairs), 2-way j-split.
// Smem (floats): Qs 32x132 | Ks x2 32x132 | Vt x2 128x36 | Ps 128x132 | stats
// ---------------------------------------------------------------------------
#define FL_QS   0
#define FL_KS0  4224
#define FL_KS1  8448
#define FL_VT0  12672
#define FL_VT1  17280
#define FL_PS   21888
#define FL_MX   38784
#define FL_SL   38912
#define FL_SC   39040
#define FL_TOT  39168

__global__ __launch_bounds__(512, 1) void flash_kernel() {
    extern __shared__ float sh[];
    float* Qs  = sh + FL_QS;
    float* Ps  = sh + FL_PS;
    float* smx = sh + FL_MX;
    float* sl  = sh + FL_SL;
    float* sc  = sh + FL_SC;

    int tid = threadIdx.x;
    int bh = blockIdx.y, b = bh >> 3, h = bh & 7;
    int i0 = blockIdx.x * 128;
    const float* qb  = g_qkv + ((size_t)(b * 768 + h * 32)) * 1024;
    const float* kb  = g_qkv + ((size_t)(b * 768 + 256 + h * 32)) * 1024;
    const float* vtg = g_vt + (size_t)bh * 1024 * 32;

    // Q tile -> smem [d][128]
    #pragma unroll
    for (int t = 0; t < 2; t++) {
        int idx = tid + t * 512;
        int d = idx >> 5, c4 = (idx & 31) * 4;
        *(float4*)&Qs[d * 132 + c4] = *(const float4*)(qb + (size_t)d * 1024 + i0 + c4);
    }
    if (tid < 128) { smx[tid] = -1e30f; sl[tid] = 0.f; }

    const int rg = tid >> 4, cg = tid & 15, ri0 = rg * 4;
    const int jhalf = tid >> 8, t8 = tid & 255;
    const int ig = t8 >> 3, dg = t8 & 7, ri = ig * 4, d0 = dg * 4;

    // prefetch jt=0
    float4 pfk[2], pfv[2];
    #pragma unroll
    for (int t = 0; t < 2; t++) {
        int idx = tid + t * 512;
        pfk[t] = *(const float4*)(kb + (size_t)(idx >> 5) * 1024 + (idx & 31) * 4);
        pfv[t] = *(const float4*)(vtg + (size_t)(idx >> 3) * 32 + (idx & 7) * 4);
    }

    u64 Oa[4][2] = {};

    for (int jt = 0; jt < 8; jt++) {
        float* Ks = sh + ((jt & 1) ? FL_KS1 : FL_KS0);
        float* Vt = sh + ((jt & 1) ? FL_VT1 : FL_VT0);
        // commit prefetched tiles
        #pragma unroll
        for (int t = 0; t < 2; t++) {
            int idx = tid + t * 512;
            *(float4*)&Ks[(idx >> 5) * 132 + (idx & 31) * 4] = pfk[t];
            *(float4*)&Vt[(idx >> 3) * 36 + (idx & 7) * 4]   = pfv[t];
        }
        __syncthreads();
        if (jt < 7) {
            int j1 = (jt + 1) * 128;
            #pragma unroll
            for (int t = 0; t < 2; t++) {
                int idx = tid + t * 512;
                pfk[t] = *(const float4*)(kb + (size_t)(idx >> 5) * 1024 + j1 + (idx & 31) * 4);
                pfv[t] = *(const float4*)(vtg + (size_t)(j1 + (idx >> 3)) * 32 + (idx & 7) * 4);
            }
        }

        // --- QK^T ---
        u64 qk[2][8] = {};
        #pragma unroll
        for (int d = 0; d < 32; d++) {
            float4 q = *(float4*)&Qs[d * 132 + ri0];
            u64 q01 = pk2(q.x, q.y), q23 = pk2(q.z, q.w);
            #pragma unroll
            for (int jj = 0; jj < 8; jj++) {
                float kv = Ks[d * 132 + cg + 16 * jj];
                u64 kp = pk2(kv, kv);
                fma2(qk[0][jj], q01, kp);
                fma2(qk[1][jj], q23, kp);
            }
        }
        float s[4][8];
        #pragma unroll
        for (int jj = 0; jj < 8; jj++) {
            upk2(s[0][jj], s[1][jj], qk[0][jj]);
            upk2(s[2][jj], s[3][jj], qk[1][jj]);
        }

        // --- online softmax (4 rows/thread) ---
        float mold[4], mnew[4], rsum[4];
        #pragma unroll
        for (int ii = 0; ii < 4; ii++) {
            float mx = s[ii][0];
            #pragma unroll
            for (int jj = 1; jj < 8; jj++) mx = fmaxf(mx, s[ii][jj]);
            #pragma unroll
            for (int msk = 1; msk < 16; msk <<= 1)
                mx = fmaxf(mx, __shfl_xor_sync(0xffffffffu, mx, msk));
            mold[ii] = smx[ri0 + ii];
            mnew[ii] = fmaxf(mold[ii], mx);
            float nk = -mnew[ii] * KK2;
            float r = 0.f;
            #pragma unroll
            for (int jj = 0; jj < 8; jj++) {
                float p = ex2(fmaf(s[ii][jj], KK2, nk));
                s[ii][jj] = p;
                r += p;
            }
            #pragma unroll
            for (int msk = 1; msk < 16; msk <<= 1)
                r += __shfl_xor_sync(0xffffffffu, r, msk);
            rsum[ii] = r;
        }
        if (cg == 0) {
            #pragma unroll
            for (int ii = 0; ii < 4; ii++) {
                float c = ex2((mold[ii] - mnew[ii]) * KK2);
                sc[ri0 + ii] = c;
                smx[ri0 + ii] = mnew[ii];
                sl[ri0 + ii] = sl[ri0 + ii] * c + rsum[ii];
            }
        }
        // store P j-major: Ps[col][i]
        #pragma unroll
        for (int jj = 0; jj < 8; jj++) {
            int col = cg + 16 * jj;
            *(float4*)&Ps[col * 132 + ri0] =
                make_float4(s[0][jj], s[1][jj], s[2][jj], s[3][jj]);
        }
        __syncthreads();

        // --- P @ V (this thread's j half) ---
        #pragma unroll
        for (int ii = 0; ii < 4; ii++) {
            float cc = sc[ri + ii];
            u64 cb = pk2(cc, cc);
            mul2(Oa[ii][0], cb);
            mul2(Oa[ii][1], cb);
        }
        int jb = jhalf * 64;
        #pragma unroll 4
        for (int jo = 0; jo < 64; jo++) {
            int j = jb + jo;
            float4 p = *(float4*)&Ps[j * 132 + ri];
            float4 v = *(float4*)&Vt[j * 36 + d0];
            u64 v01 = pk2(v.x, v.y), v23 = pk2(v.z, v.w);
            u64 pbx;
            pbx = pk2(p.x, p.x); fma2(Oa[0][0], pbx, v01); fma2(Oa[0][1], pbx, v23);
            pbx = pk2(p.y, p.y); fma2(Oa[1][0], pbx, v01); fma2(Oa[1][1], pbx, v23);
            pbx = pk2(p.z, p.z); fma2(Oa[2][0], pbx, v01); fma2(Oa[2][1], pbx, v23);
            pbx = pk2(p.w, p.w); fma2(Oa[3][0], pbx, v01); fma2(Oa[3][1], pbx, v23);
        }
    }
    __syncthreads();

    // reduce the two j-halves through Ps, scale, store [d][s]
    float o[4][4];
    #pragma unroll
    for (int ii = 0; ii < 4; ii++) {
        upk2(o[ii][0], o[ii][1], Oa[ii][0]);
        upk2(o[ii][2], o[ii][3], Oa[ii][1]);
    }
    if (jhalf == 1) {
        #pragma unroll
        for (int ii = 0; ii < 4; ii++)
            *(float4*)&Ps[(ri + ii) * 132 + d0] =
                make_float4(o[ii][0], o[ii][1], o[ii][2], o[ii][3]);
    }
    __syncthreads();
    if (jhalf == 0) {
        float* ob = g_att + ((size_t)(b * 256 + h * 32)) * 1024 + i0;
        #pragma unroll
        for (int ii = 0; ii < 4; ii++) {
            float4 part = *(float4*)&Ps[(ri + ii) * 132 + d0];
            float linv = 1.f / sl[ri + ii];
            o[ii][0] = (o[ii][0] + part.x) * linv;
            o[ii][1] = (o[ii][1] + part.y) * linv;
            o[ii][2] = (o[ii][2] + part.z) * linv;
            o[ii][3] = (o[ii][3] + part.w) * linv;
        }
        #pragma unroll
        for (int dd = 0; dd < 4; dd++)
            *(float4*)&ob[(size_t)(d0 + dd) * 1024 + ri] =
                make_float4(o[0][dd], o[1][dd], o[2][dd], o[3][dd]);
    }
}

// ---------------------------------------------------------------------------
extern "C" void kernel_launch(void* const* d_in, const int* in_sizes, int n_in,
                              void* d_out, int out_size) {
    const float* x      = (const float*)d_in[0];
    const float* gamma  = (const float*)d_in[1];
    const float* beta   = (const float*)d_in[2];
    const float* w_qkv  = (const float*)d_in[3];
    const float* w_proj = (const float*)d_in[4];
    const float* b_proj = (const float*)d_in[5];
    float* out = (float*)d_out;

    float* qkv; cudaGetSymbolAddress((void**)&qkv, g_qkv);
    float* att; cudaGetSymbolAddress((void**)&att, g_att);

    static int smem_set = 0;
    const int FLASH_SMEM = FL_TOT * 4;
    if (!smem_set) {
        cudaFuncSetAttribute(flash_kernel,
                             cudaFuncAttributeMaxDynamicSharedMemorySize,
                             FLASH_SMEM);
        smem_set = 1;
    }

    // 1. GroupNorm stats -> affine coefficients
    gnstat_kernel<<<B_ * 32, 256>>>(x, gamma, beta);

    // 2. QKV GEMM (fused GN affine; V written transposed to g_vt)
    {
        dim3 grid(S_ / 64, (3 * C_) / 128, B_);
        gemm_f2<128, 8, false, true, true><<<grid, 256>>>(
            w_qkv, x, qkv, nullptr, nullptr, 3 * C_, C_);
    }

    // 3. Fused flash attention (512 threads, double-buffered tiles)
    {
        dim3 grid(S_ / 128, B_ * HEADS_);
        flash_kernel<<<grid, 512, FLASH_SMEM>>>();
    }

    // 4. Proj + bias + residual
    {
        dim3 grid(S_ / 64, C_ / 64, B_);
        gemm_f2<64, 4, true, false, false><<<grid, 256>>>(
            w_proj, att, out, b_proj, x, C_, C_);
    }
}